// round 17
// baseline (speedup 1.0000x reference)
#include <cuda_runtime.h>
#include <cuda_fp16.h>
#include <stdint.h>
#include <math.h>

// Problem constants
#define Bn 8
#define Tn 1024
#define En 1024
#define Hn 16
#define HDn 64
#define FFn 4096
#define E3n 3072
#define TOK 8192          // B*T
#define BHn 128           // B*H
#define SCALE_Q 0.125f    // 64^-0.5 (folded into Q weights/bias at cvt time)
#define LN_EPS 1e-12f

// ======================= PTX helpers (sm_80+ features only) =======================
__device__ __forceinline__ uint32_t smem_u32(const void* p) {
    uint32_t a;
    asm("{ .reg .u64 t; cvta.to.shared.u64 t, %1; cvt.u32.u64 %0, t; }" : "=r"(a) : "l"(p));
    return a;
}
#define CP_ASYNC16(dst, src) \
    asm volatile("cp.async.cg.shared.global [%0], [%1], 16;" :: "r"(dst), "l"(src) : "memory")
#define CP_COMMIT() asm volatile("cp.async.commit_group;" ::: "memory")
#define CP_WAIT1()  asm volatile("cp.async.wait_group 1;" ::: "memory")
#define LDSM_X4(r0, r1, r2, r3, addr) \
    asm volatile("ldmatrix.sync.aligned.m8n8.x4.shared.b16 {%0,%1,%2,%3}, [%4];" \
        : "=r"(r0), "=r"(r1), "=r"(r2), "=r"(r3) : "r"(addr))
#define LDSM_X4_T(r0, r1, r2, r3, addr) \
    asm volatile("ldmatrix.sync.aligned.m8n8.x4.trans.shared.b16 {%0,%1,%2,%3}, [%4];" \
        : "=r"(r0), "=r"(r1), "=r"(r2), "=r"(r3) : "r"(addr))
#define MMA16816(d, a, b) \
    asm volatile("mma.sync.aligned.m16n8k16.row.col.f32.f16.f16.f32 " \
        "{%0,%1,%2,%3}, {%4,%5,%6,%7}, {%8,%9}, {%0,%1,%2,%3};" \
        : "+f"((d)[0]), "+f"((d)[1]), "+f"((d)[2]), "+f"((d)[3]) \
        : "r"((a)[0]), "r"((a)[1]), "r"((a)[2]), "r"((a)[3]), "r"((b)[0]), "r"((b)[1]))

// ---------------- static scratch (no allocations allowed) ----------------
__device__ __half g_qkvh[(long)TOK * E3n];             // fp16 qkv (Q pre-scaled)
__device__ float g_tmp[TOK * En];
__device__ float g_x1[TOK * En];
__device__ int   g_len[Bn];
__device__ float g_inb[E3n];                           // in_b with Q part pre-scaled
__device__ __half g_xh[(long)TOK * En];
__device__ __half g_attnh[(long)TOK * En];
__device__ __half g_x1h[(long)TOK * En];
__device__ __half g_ffnh[(long)TOK * FFn];
__device__ __half g_inwh[(long)E3n * En];
__device__ __half g_outwh[(long)En * En];
__device__ __half g_fc1wh[(long)FFn * En];
__device__ __half g_fc2wh[(long)En * FFn];

// ---------------- fp32 -> fp16 convert (8 elems/thread) ----------------
__global__ void __launch_bounds__(256) cvt_kernel(const float* __restrict__ src,
                                                  __half* __restrict__ dst, long n8)
{
    long i = (long)blockIdx.x * 256 + threadIdx.x;
    if (i >= n8) return;
    float4 a = ((const float4*)src)[2 * i];
    float4 b = ((const float4*)src)[2 * i + 1];
    __align__(16) __half o[8];
    o[0] = __float2half_rn(a.x); o[1] = __float2half_rn(a.y);
    o[2] = __float2half_rn(a.z); o[3] = __float2half_rn(a.w);
    o[4] = __float2half_rn(b.x); o[5] = __float2half_rn(b.y);
    o[6] = __float2half_rn(b.z); o[7] = __float2half_rn(b.w);
    ((uint4*)dst)[i] = *(const uint4*)o;
}

// ---- in_w cvt with Q rows (row < En) pre-scaled by SCALE_Q (exact pow2) ----
__global__ void __launch_bounds__(256) cvt_qw_kernel(const float* __restrict__ src,
                                                     __half* __restrict__ dst, long n8)
{
    long i = (long)blockIdx.x * 256 + threadIdx.x;
    if (i >= n8) return;
    long row = (8 * i) >> 10;            // En = 1024 elements per row
    float s = (row < En) ? SCALE_Q : 1.0f;
    float4 a = ((const float4*)src)[2 * i];
    float4 b = ((const float4*)src)[2 * i + 1];
    __align__(16) __half o[8];
    o[0] = __float2half_rn(a.x * s); o[1] = __float2half_rn(a.y * s);
    o[2] = __float2half_rn(a.z * s); o[3] = __float2half_rn(a.w * s);
    o[4] = __float2half_rn(b.x * s); o[5] = __float2half_rn(b.y * s);
    o[6] = __float2half_rn(b.z * s); o[7] = __float2half_rn(b.w * s);
    ((uint4*)dst)[i] = *(const uint4*)o;
}

// ---- in_b with Q part pre-scaled ----
__global__ void __launch_bounds__(256) scale_bias_kernel(const float* __restrict__ src,
                                                         float* __restrict__ dst)
{
    int i = blockIdx.x * 256 + threadIdx.x;
    if (i >= E3n) return;
    dst[i] = src[i] * ((i < En) ? SCALE_Q : 1.0f);
}

// ---------------- mask dtype detection + lengths ----------------
__global__ void len_kernel(const void* maskp) {
    __shared__ int s_kind;   // 0=i32, 1=u8, 2=f32
    __shared__ int s_len[Bn];
    int t = threadIdx.x;
    if (t == 0) s_kind = 0;
    if (t < Bn) s_len[t] = Tn;
    __syncthreads();
    const unsigned int* w = (const unsigned int*)maskp;
    for (int i = t; i < 2048; i += blockDim.x) {
        unsigned int v = w[i];
        if (v == 0x3F800000u) atomicMax(&s_kind, 2);
        else if (v > 1u)      atomicMax(&s_kind, 1);
    }
    __syncthreads();
    int kind = s_kind;
    const unsigned char* mb = (const unsigned char*)maskp;
    const int* mi = (const int*)maskp;
    const float* mf = (const float*)maskp;
    for (int i = t; i < Bn * Tn; i += blockDim.x) {
        int b = i >> 10, tt = i & (Tn - 1);
        int m;
        if (kind == 1)      m = (int)mb[i];
        else if (kind == 2) m = (mf[i] != 0.0f);
        else                m = mi[i];
        if (m) atomicMin(&s_len[b], tt);
    }
    __syncthreads();
    if (t < Bn) g_len[t] = s_len[t];
}

// ============ mma.sync GEMM (proven R9): C[M,N] = A[M,K] * B[N,K]^T + bias ============
// CTA 128x128, warp 64x32, 128 regs -> 2 CTAs/SM = full RF, 4 warps/SMSP.
// Single-barrier 3-stage pipeline: wait(<=1) -> sync -> issue(c+2) -> compute(c).
#define GST 3
#define STAGE_BYTES 32768

template<bool RELU, bool HALF_OUT>
__global__ void __launch_bounds__(256) gemm_mma(
    const __half* __restrict__ A2,
    const __half* __restrict__ B2,
    const float* __restrict__ bias,
    void* __restrict__ Cv, int N, int K2)
{
    extern __shared__ char smem[];
    uint32_t sb = smem_u32(smem);
    int tid = threadIdx.x, lane = tid & 31, w = tid >> 5;
    int m0 = blockIdx.y * 128, n0 = blockIdx.x * 128;
    int warpM = (w >> 2) * 64, warpN = (w & 3) * 32;
    const int CH = K2 >> 6;

    auto issue = [&](int c) {
        if (c < CH) {
            uint32_t base = sb + (c % GST) * STAGE_BYTES;
            long kb = (long)c * 64;
#pragma unroll
            for (int i = 0; i < 4; i++) {
                int flat = i * 256 + tid;
                int row = flat >> 3;
                int seg = flat & 7;
                uint32_t off = (uint32_t)(row * 128 + ((seg * 16) ^ ((row & 7) * 16)));
                CP_ASYNC16(base + off,         A2 + (long)(m0 + row) * K2 + kb + seg * 8);
                CP_ASYNC16(base + 16384 + off, B2 + (long)(n0 + row) * K2 + kb + seg * 8);
            }
        }
        CP_COMMIT();
    };
    issue(0); issue(1);

    float acc[4][4][4];
#pragma unroll
    for (int i = 0; i < 4; i++)
#pragma unroll
        for (int j = 0; j < 4; j++)
#pragma unroll
            for (int k = 0; k < 4; k++) acc[i][j][k] = 0.0f;

    int mrow = warpM + (lane & 7) + ((lane >> 3) & 1) * 8;
    int acol = (lane >> 4) * 16;
    int nrow = warpN + (lane & 7) + ((lane >> 4) & 1) * 8;
    int bcol = ((lane >> 3) & 1) * 16;

    for (int c = 0; c < CH; c++) {
        CP_WAIT1();
        __syncthreads();
        issue(c + 2);
        uint32_t sA = sb + (c % GST) * STAGE_BYTES;
        uint32_t sB = sA + 16384;
#pragma unroll
        for (int ks = 0; ks < 4; ks++) {
            uint32_t af[4][4];
#pragma unroll
            for (int mi = 0; mi < 4; mi++) {
                int m = mrow + mi * 16;
                uint32_t addr = sA + m * 128 + ((ks * 32 + acol) ^ ((m & 7) * 16));
                LDSM_X4(af[mi][0], af[mi][1], af[mi][2], af[mi][3], addr);
            }
            uint32_t bf[4][2];
#pragma unroll
            for (int nb = 0; nb < 2; nb++) {
                int n = nrow + nb * 16;
                uint32_t addr = sB + n * 128 + ((ks * 32 + bcol) ^ ((n & 7) * 16));
                uint32_t r0, r1, r2, r3;
                LDSM_X4(r0, r1, r2, r3, addr);
                bf[nb * 2][0] = r0;     bf[nb * 2][1] = r1;
                bf[nb * 2 + 1][0] = r2; bf[nb * 2 + 1][1] = r3;
            }
#pragma unroll
            for (int mi = 0; mi < 4; mi++)
#pragma unroll
                for (int ni = 0; ni < 4; ni++)
                    MMA16816(acc[mi][ni], af[mi], bf[ni]);
        }
    }

#pragma unroll
    for (int mi = 0; mi < 4; mi++) {
        int r = m0 + warpM + mi * 16 + (lane >> 2);
#pragma unroll
        for (int ni = 0; ni < 4; ni++) {
            int col = n0 + warpN + ni * 8 + (lane & 3) * 2;
            float b0 = bias[col], b1 = bias[col + 1];
            float v0 = acc[mi][ni][0] + b0, v1 = acc[mi][ni][1] + b1;
            float v2 = acc[mi][ni][2] + b0, v3 = acc[mi][ni][3] + b1;
            if (RELU) {
                v0 = fmaxf(v0, 0.0f); v1 = fmaxf(v1, 0.0f);
                v2 = fmaxf(v2, 0.0f); v3 = fmaxf(v3, 0.0f);
            }
            if (HALF_OUT) {
                __half* C = (__half*)Cv;
                __align__(4) __half o[2];
                o[0] = __float2half_rn(v0); o[1] = __float2half_rn(v1);
                *(uint32_t*)(C + (long)r * N + col) = *(const uint32_t*)o;
                o[0] = __float2half_rn(v2); o[1] = __float2half_rn(v3);
                *(uint32_t*)(C + (long)(r + 8) * N + col) = *(const uint32_t*)o;
            } else {
                float* C = (float*)Cv;
                float2 p0; p0.x = v0; p0.y = v1;
                float2 p1; p1.x = v2; p1.y = v3;
                *(float2*)(C + (long)r * N + col) = p0;
                *(float2*)(C + (long)(r + 8) * N + col) = p1;
            }
        }
    }
}

// ---------------- shared tile loader: 64 rows x 128B, swizzled ----------------
__device__ __forceinline__ void load_tile64x128(uint32_t dst, const __half* src,
                                                long strideHalfs, int tid)
{
#pragma unroll
    for (int i = 0; i < 2; i++) {
        int flat = i * 256 + tid;
        int row = flat >> 3;
        int seg = flat & 7;
        uint32_t off = (uint32_t)(row * 128 + ((seg * 16) ^ ((row & 7) * 16)));
        CP_ASYNC16(dst + off, src + (long)row * strideHalfs + seg * 8);
    }
}

// ============ fused flash attention: qkvh -> attnh (fp16) ============
// grid (T/128 q-blocks, B*H). 8 warps x m16 = 128 q rows. K-tiles of 64, causal.
// Q fragments register-resident (loaded once); Q pre-scaled at cvt time.
// 3-stage K/V pipeline, single barrier per tile. smem: Q 16KB + K 3x8 + V 3x8 = 64KB.
__global__ void __launch_bounds__(256) fa_kernel(const __half* __restrict__ qkvh,
                                                 __half* __restrict__ attnh)
{
    int qb = blockIdx.x, bh = blockIdx.y;
    int b = bh >> 4, h = bh & 15;
    int q0 = qb * 128;
    extern __shared__ char smem[];
    uint32_t sQ = smem_u32(smem);
    uint32_t sK = sQ + 16384;
    uint32_t sV = sK + 24576;
    int tid = threadIdx.x, lane = tid & 31, w = tid >> 5;

    const __half* qbase = qkvh + (long)(b * Tn + q0) * E3n + HDn * h;
    const __half* kbase = qkvh + (long)(b * Tn) * E3n + En + HDn * h;
    const __half* vbase = qkvh + (long)(b * Tn) * E3n + 2 * En + HDn * h;
    int len = g_len[b];
    const int KT = (q0 + 127) >> 6;     // inclusive last k-tile (>=1)

    auto issue = [&](int kt) {
        if (kt <= KT) {
            uint32_t dk = sK + (kt % 3) * 8192;
            uint32_t dv = sV + (kt % 3) * 8192;
            load_tile64x128(dk, kbase + (long)kt * 64 * E3n, E3n, tid);
            load_tile64x128(dv, vbase + (long)kt * 64 * E3n, E3n, tid);
        }
        CP_COMMIT();
    };

    load_tile64x128(sQ, qbase, E3n, tid);
    load_tile64x128(sQ + 8192, qbase + (long)64 * E3n, E3n, tid);
    issue(0);          // group 0: Q + K0/V0
    issue(1);          // group 1: K1/V1

    int qrow = w * 16 + (lane >> 2);                     // row in [0,128)
    int kmax0 = min(q0 + qrow, len - 1);
    int kmax1 = min(q0 + qrow + 8, len - 1);
    int mrow = w * 16 + (lane & 7) + ((lane >> 3) & 1) * 8;  // Q A-ldsm row
    int acol = (lane >> 4) * 16;
    int nrow0 = (lane & 7) + ((lane >> 4) & 1) * 8;          // K B-ldsm row
    int bcol = ((lane >> 3) & 1) * 16;
    int wmaskref = min(q0 + w * 16, len - 1);            // min kmax over warp rows

    float m0r = -1e30f, m1r = -1e30f, l0 = 0.0f, l1 = 0.0f;
    float o[8][4];
#pragma unroll
    for (int i = 0; i < 8; i++)
#pragma unroll
        for (int j = 0; j < 4; j++) o[i][j] = 0.0f;

    uint32_t qf[4][4];                                   // register-resident Q
    bool qloaded = false;

    for (int kt = 0; kt <= KT; kt++) {
        CP_WAIT1();
        __syncthreads();
        issue(kt + 2);
        uint32_t sk = sK + (kt % 3) * 8192;
        uint32_t sv = sV + (kt % 3) * 8192;

        if (!qloaded) {
            qloaded = true;
#pragma unroll
            for (int ks = 0; ks < 4; ks++)
                LDSM_X4(qf[ks][0], qf[ks][1], qf[ks][2], qf[ks][3],
                        sQ + mrow * 128 + ((ks * 32 + acol) ^ ((mrow & 7) * 16)));
        }

        // ---- S = Q . K^T : m16 x n64 per warp ----
        float c[8][4];
#pragma unroll
        for (int i = 0; i < 8; i++)
#pragma unroll
            for (int j = 0; j < 4; j++) c[i][j] = 0.0f;
#pragma unroll
        for (int ks = 0; ks < 4; ks++) {
#pragma unroll
            for (int nb = 0; nb < 4; nb++) {
                int n = nrow0 + nb * 16;
                uint32_t r0, r1, r2, r3;
                LDSM_X4(r0, r1, r2, r3, sk + n * 128 + ((ks * 32 + bcol) ^ ((n & 7) * 16)));
                uint32_t bfa[2] = { r0, r1 }, bfb[2] = { r2, r3 };
                MMA16816(c[nb * 2], qf[ks], bfa);
                MMA16816(c[nb * 2 + 1], qf[ks], bfb);
            }
        }

        // ---- mask + tile row max (scale already folded into Q) ----
        bool needmask = (kt * 64 + 63 > wmaskref);
        int colb = kt * 64 + (lane & 3) * 2;
        float mt0 = -1e30f, mt1 = -1e30f;
#pragma unroll
        for (int nf = 0; nf < 8; nf++) {
            if (needmask) {
                int col = colb + nf * 8;
                if (col > kmax0)     c[nf][0] = -1e30f;
                if (col + 1 > kmax0) c[nf][1] = -1e30f;
                if (col > kmax1)     c[nf][2] = -1e30f;
                if (col + 1 > kmax1) c[nf][3] = -1e30f;
            }
            mt0 = fmaxf(mt0, fmaxf(c[nf][0], c[nf][1]));
            mt1 = fmaxf(mt1, fmaxf(c[nf][2], c[nf][3]));
        }
        mt0 = fmaxf(mt0, __shfl_xor_sync(0xFFFFFFFFu, mt0, 1));
        mt0 = fmaxf(mt0, __shfl_xor_sync(0xFFFFFFFFu, mt0, 2));
        mt1 = fmaxf(mt1, __shfl_xor_sync(0xFFFFFFFFu, mt1, 1));
        mt1 = fmaxf(mt1, __shfl_xor_sync(0xFFFFFFFFu, mt1, 2));

        // ---- online softmax update ----
        float mn0 = fmaxf(m0r, mt0), mn1 = fmaxf(m1r, mt1);
        float cor0 = __expf(m0r - mn0), cor1 = __expf(m1r - mn1);
        m0r = mn0; m1r = mn1;
        float s0 = 0.0f, s1 = 0.0f;
        uint32_t ph0[8], ph1[8];
#pragma unroll
        for (int nf = 0; nf < 8; nf++) {
            float e0 = __expf(c[nf][0] - mn0);
            float e1 = __expf(c[nf][1] - mn0);
            float e2 = __expf(c[nf][2] - mn1);
            float e3 = __expf(c[nf][3] - mn1);
            s0 += e0 + e1; s1 += e2 + e3;
            __half2 hp0 = __floats2half2_rn(e0, e1);
            __half2 hp1 = __floats2half2_rn(e2, e3);
            ph0[nf] = *(uint32_t*)&hp0;
            ph1[nf] = *(uint32_t*)&hp1;
        }
        s0 += __shfl_xor_sync(0xFFFFFFFFu, s0, 1);
        s0 += __shfl_xor_sync(0xFFFFFFFFu, s0, 2);
        s1 += __shfl_xor_sync(0xFFFFFFFFu, s1, 1);
        s1 += __shfl_xor_sync(0xFFFFFFFFu, s1, 2);
        l0 = l0 * cor0 + s0;
        l1 = l1 * cor1 + s1;
#pragma unroll
        for (int nf = 0; nf < 8; nf++) {
            o[nf][0] *= cor0; o[nf][1] *= cor0;
            o[nf][2] *= cor1; o[nf][3] *= cor1;
        }

        // ---- O += P . V  (V via ldmatrix.trans from [k][d] tile) ----
#pragma unroll
        for (int kf = 0; kf < 4; kf++) {
            uint32_t a[4] = { ph0[kf * 2], ph1[kf * 2], ph0[kf * 2 + 1], ph1[kf * 2 + 1] };
            int krow = kf * 16 + ((lane >> 3) & 1) * 8 + (lane & 7);
#pragma unroll
            for (int db = 0; db < 2; db++) {
                int dcolb = ((lane >> 4) * 8 + db * 32) * 2;
                uint32_t r0, r1, r2, r3;
                LDSM_X4_T(r0, r1, r2, r3,
                          sv + krow * 128 + (dcolb ^ ((krow & 7) * 16)));
                uint32_t bfa[2] = { r0, r1 }, bfb[2] = { r2, r3 };
                MMA16816(o[db * 4 + 0], a, bfa);
                MMA16816(o[db * 4 + 1], a, bfb);
                int dcolb2 = dcolb + 32;
                LDSM_X4_T(r0, r1, r2, r3,
                          sv + krow * 128 + (dcolb2 ^ ((krow & 7) * 16)));
                uint32_t bfc[2] = { r0, r1 }, bfd[2] = { r2, r3 };
                MMA16816(o[db * 4 + 2], a, bfc);
                MMA16816(o[db * 4 + 3], a, bfd);
            }
        }
    }

    // ---- epilogue: O / l -> fp16 attn ----
    float inv0 = 1.0f / l0, inv1 = 1.0f / l1;
    long tok = (long)b * Tn + q0 + qrow;
#pragma unroll
    for (int nf = 0; nf < 8; nf++) {
        int d = h * 64 + nf * 8 + (lane & 3) * 2;
        __half2 w0 = __floats2half2_rn(o[nf][0] * inv0, o[nf][1] * inv0);
        __half2 w1 = __floats2half2_rn(o[nf][2] * inv1, o[nf][3] * inv1);
        *(uint32_t*)(attnh + tok * En + d) = *(uint32_t*)&w0;
        *(uint32_t*)(attnh + (tok + 8) * En + d) = *(uint32_t*)&w1;
    }
}

// -------- residual add + LayerNorm: float4 vectorized, warp-shfl reduce --------
__global__ void __launch_bounds__(256) ln_kernel(const float* __restrict__ res,
                                                 const float* __restrict__ y,
                                                 const float* __restrict__ w,
                                                 const float* __restrict__ bb,
                                                 float* __restrict__ out,
                                                 __half* __restrict__ outs)
{
    long r = blockIdx.x;
    int t = threadIdx.x, lane = t & 31, wid = t >> 5;
    const float4* r4 = (const float4*)(res + r * En);
    const float4* y4 = (const float4*)(y + r * En);
    __shared__ float ws[8], wss[8];
    float4 a = r4[t], c4 = y4[t];
    float4 v;
    v.x = a.x + c4.x; v.y = a.y + c4.y; v.z = a.z + c4.z; v.w = a.w + c4.w;
    float s = v.x + v.y + v.z + v.w;
    float ss = v.x * v.x + v.y * v.y + v.z * v.z + v.w * v.w;
#pragma unroll
    for (int sh = 16; sh > 0; sh >>= 1) {
        s  += __shfl_xor_sync(0xFFFFFFFFu, s, sh);
        ss += __shfl_xor_sync(0xFFFFFFFFu, ss, sh);
    }
    if (lane == 0) { ws[wid] = s; wss[wid] = ss; }
    __syncthreads();
    if (wid == 0) {
        float aa = (lane < 8) ? ws[lane] : 0.0f;
        float cc = (lane < 8) ? wss[lane] : 0.0f;
#pragma unroll
        for (int sh = 4; sh > 0; sh >>= 1) {
            aa += __shfl_xor_sync(0xFFFFFFFFu, aa, sh);
            cc += __shfl_xor_sync(0xFFFFFFFFu, cc, sh);
        }
        if (lane == 0) { ws[0] = aa; wss[0] = cc; }
    }
    __syncthreads();
    float mean = ws[0] * (1.0f / En);
    float var  = wss[0] * (1.0f / En) - mean * mean;
    float inv  = rsqrtf(var + LN_EPS);
    float4 wv = ((const float4*)w)[t];
    float4 bv = ((const float4*)bb)[t];
    float4 o;
    o.x = wv.x * (v.x - mean) * inv + bv.x;
    o.y = wv.y * (v.y - mean) * inv + bv.y;
    o.z = wv.z * (v.z - mean) * inv + bv.z;
    o.w = wv.w * (v.w - mean) * inv + bv.w;
    ((float4*)(out + r * En))[t] = o;
    if (outs) {
        __align__(8) __half hh[4];
        hh[0] = __float2half_rn(o.x); hh[1] = __float2half_rn(o.y);
        hh[2] = __float2half_rn(o.z); hh[3] = __float2half_rn(o.w);
        ((uint2*)(outs + r * En))[t] = *(const uint2*)hh;
    }
}

// ---------------- launch ----------------
static inline void cvt(const float* src, __half* dst, long n) {
    long n8 = n >> 3;
    cvt_kernel<<<(unsigned)((n8 + 255) / 256), 256>>>(src, dst, n8);
}

extern "C" void kernel_launch(void* const* d_in, const int* in_sizes, int n_in,
                              void* d_out, int out_size)
{
    const float* x     = (const float*)d_in[0];
    const float* in_w  = (const float*)d_in[1];
    const float* in_b  = (const float*)d_in[2];
    const float* out_w = (const float*)d_in[3];
    const float* out_b = (const float*)d_in[4];
    const float* fc1_w = (const float*)d_in[5];
    const float* fc1_b = (const float*)d_in[6];
    const float* fc2_w = (const float*)d_in[7];
    const float* fc2_b = (const float*)d_in[8];
    const float* ln1_w = (const float*)d_in[9];
    const float* ln1_b = (const float*)d_in[10];
    const float* ln2_w = (const float*)d_in[11];
    const float* ln2_b = (const float*)d_in[12];
    const void*  pad_mask = d_in[13];
    float* out = (float*)d_out;

    float *tmp, *x1, *inb;
    cudaGetSymbolAddress((void**)&tmp, g_tmp);
    cudaGetSymbolAddress((void**)&x1,  g_x1);
    cudaGetSymbolAddress((void**)&inb, g_inb);
    __half *qkvh, *xh, *attnh, *x1h, *ffnh, *inwh, *outwh, *fc1wh, *fc2wh;
    cudaGetSymbolAddress((void**)&qkvh,  g_qkvh);
    cudaGetSymbolAddress((void**)&xh,    g_xh);
    cudaGetSymbolAddress((void**)&attnh, g_attnh);
    cudaGetSymbolAddress((void**)&x1h,   g_x1h);
    cudaGetSymbolAddress((void**)&ffnh,  g_ffnh);
    cudaGetSymbolAddress((void**)&inwh,  g_inwh);
    cudaGetSymbolAddress((void**)&outwh, g_outwh);
    cudaGetSymbolAddress((void**)&fc1wh, g_fc1wh);
    cudaGetSymbolAddress((void**)&fc2wh, g_fc2wh);

    const int GSMEM = GST * STAGE_BYTES;   // 96 KB
    cudaFuncSetAttribute(gemm_mma<false, false>, cudaFuncAttributeMaxDynamicSharedMemorySize, GSMEM);
    cudaFuncSetAttribute(gemm_mma<false, true>,  cudaFuncAttributeMaxDynamicSharedMemorySize, GSMEM);
    cudaFuncSetAttribute(gemm_mma<true, true>,   cudaFuncAttributeMaxDynamicSharedMemorySize, GSMEM);
    cudaFuncSetAttribute(fa_kernel, cudaFuncAttributeMaxDynamicSharedMemorySize, 65536);

    // 0. sequence lengths
    len_kernel<<<1, 256>>>(pad_mask);

    // 1. QKV projection -> fp16 qkvh (Q weights/bias pre-scaled by SCALE_Q)
    cvt(x, xh, (long)TOK * En);
    {
        long n8 = ((long)E3n * En) >> 3;
        cvt_qw_kernel<<<(unsigned)((n8 + 255) / 256), 256>>>(in_w, inwh, n8);
    }
    scale_bias_kernel<<<(E3n + 255) / 256, 256>>>(in_b, inb);
    gemm_mma<false, true><<<dim3(E3n / 128, TOK / 128), 256, GSMEM>>>(xh, inwh, inb, qkvh, E3n, En);

    // 2. fused flash attention -> fp16 attnh
    fa_kernel<<<dim3(Tn / 128, BHn), 256, 65536>>>(qkvh, attnh);

    // 3. output projection
    cvt(out_w, outwh, (long)En * En);
    gemm_mma<false, false><<<dim3(En / 128, TOK / 128), 256, GSMEM>>>(attnh, outwh, out_b, tmp, En, En);

    // 4. residual + LN1
    ln_kernel<<<TOK, 256>>>(x, tmp, ln1_w, ln1_b, x1, x1h);

    // 5. FC1 + ReLU -> fp16 ffnh
    cvt(fc1_w, fc1wh, (long)FFn * En);
    gemm_mma<true, true><<<dim3(FFn / 128, TOK / 128), 256, GSMEM>>>(x1h, fc1wh, fc1_b, ffnh, FFn, En);

    // 6. FC2
    cvt(fc2_w, fc2wh, (long)En * FFn);
    gemm_mma<false, false><<<dim3(En / 128, TOK / 128), 256, GSMEM>>>(ffnh, fc2wh, fc2_b, tmp, En, FFn);

    // 7. residual + LN2 -> out
    ln_kernel<<<TOK, 256>>>(x1, tmp, ln2_w, ln2_b, out, (half*)nullptr);
}